// round 1
// baseline (speedup 1.0000x reference)
#include <cuda_runtime.h>
#include <cuda_bf16.h>

#define N_NODES 100000
#define D_FEAT 128
#define K_NEIGH 16

// Scratch: hidden activations and aggregated neighbor means (51.2 MB each).
__device__ float g_h[(size_t)N_NODES * D_FEAT];
__device__ float g_agg[(size_t)N_NODES * D_FEAT];

// ---------------------------------------------------------------------------
// Gather + mean: one warp per node. Lane c handles columns [4c, 4c+4).
// Neighbor row = 512B contiguous -> fully coalesced warp read (L2-resident).
// ---------------------------------------------------------------------------
__global__ void gather_mean_kernel(const float* __restrict__ ext_h,
                                   const int* __restrict__ idx,
                                   int layer) {
    const float* __restrict__ h = (layer == 0) ? ext_h : g_h;

    int gwarp = (blockIdx.x * blockDim.x + threadIdx.x) >> 5;
    int lane = threadIdx.x & 31;
    if (gwarp >= N_NODES) return;

    // Coalesced index load: lanes 0..15 load the 16 neighbor ids.
    const int* ip = idx + (size_t)gwarp * K_NEIGH;
    int myidx = (lane < K_NEIGH) ? ip[lane] : 0;

    int c = lane * 4;
    float4 s = make_float4(0.f, 0.f, 0.f, 0.f);
#pragma unroll
    for (int k = 0; k < K_NEIGH; ++k) {
        int r = __shfl_sync(0xffffffffu, myidx, k);
        float4 v = *reinterpret_cast<const float4*>(h + (size_t)r * D_FEAT + c);
        s.x += v.x; s.y += v.y; s.z += v.z; s.w += v.w;
    }
    const float inv = 1.0f / (float)K_NEIGH;
    s.x *= inv; s.y *= inv; s.z *= inv; s.w *= inv;
    *reinterpret_cast<float4*>(g_agg + (size_t)gwarp * D_FEAT + c) = s;
}

// ---------------------------------------------------------------------------
// Fused SAGE GEMM: z = [h | agg] @ W + b, optional ReLU at store.
// M = N_NODES, N = 128, K = 256. Tiles: BM=128, BN=128, BK=16, 256 threads,
// 8x8 microtile per thread.
// ---------------------------------------------------------------------------
#define BM 128
#define BN 128
#define BK 16

__global__ __launch_bounds__(256, 2)
void sage_gemm_kernel(const float* __restrict__ ext_a,   // feats   (used when layer==0)
                      const float* __restrict__ W,       // [256,128] row-major
                      const float* __restrict__ bias,    // [128]
                      float* __restrict__ ext_out,       // d_out   (used when layer==1)
                      int M, int layer) {
    const float* __restrict__ A1 = (layer == 0) ? ext_a : g_h;  // self half (k < 128)
    const float* __restrict__ A2 = g_agg;                        // agg half  (k >= 128)
    float* __restrict__ out = (layer == 0) ? g_h : ext_out;
    const bool do_relu = (layer == 0);

    __shared__ float As[BK][BM];   // transposed A tile
    __shared__ float Bs[BK][BN];

    const int tid = threadIdx.x;
    const int tx = tid & 15;       // col group 0..15
    const int ty = tid >> 4;       // row group 0..15
    const int row0 = blockIdx.x * BM;

    float acc[8][8];
#pragma unroll
    for (int i = 0; i < 8; ++i)
#pragma unroll
        for (int j = 0; j < 8; ++j) acc[i][j] = 0.f;

    for (int k0 = 0; k0 < 2 * D_FEAT; k0 += BK) {
        const float* __restrict__ src = (k0 < D_FEAT) ? (A1 + k0) : (A2 + (k0 - D_FEAT));

        // ---- load A tile: 128 rows x 16 k, as 512 float4 (2 per thread) ----
#pragma unroll
        for (int i = 0; i < 2; ++i) {
            int linear = tid + i * 256;        // float4 index 0..511
            int r  = linear >> 2;              // 0..127
            int kq = (linear & 3) << 2;        // 0,4,8,12
            float4 v = make_float4(0.f, 0.f, 0.f, 0.f);
            int grow = row0 + r;
            if (grow < M)
                v = *reinterpret_cast<const float4*>(src + (size_t)grow * D_FEAT + kq);
            As[kq + 0][r] = v.x;
            As[kq + 1][r] = v.y;
            As[kq + 2][r] = v.z;
            As[kq + 3][r] = v.w;
        }

        // ---- load B tile: 16 k x 128 n ----
#pragma unroll
        for (int i = 0; i < 2; ++i) {
            int linear = tid + i * 256;        // float4 index 0..511
            int kk = linear >> 5;              // 0..15
            int nq = (linear & 31) << 2;       // 0..124
            *reinterpret_cast<float4*>(&Bs[kk][nq]) =
                *reinterpret_cast<const float4*>(W + (size_t)(k0 + kk) * BN + nq);
        }
        __syncthreads();

        // ---- 8x8 microtile FMA over BK ----
#pragma unroll
        for (int kk = 0; kk < BK; ++kk) {
            float a[8], b[8];
            float4 a0 = *reinterpret_cast<const float4*>(&As[kk][ty * 8]);
            float4 a1 = *reinterpret_cast<const float4*>(&As[kk][ty * 8 + 4]);
            float4 b0 = *reinterpret_cast<const float4*>(&Bs[kk][tx * 8]);
            float4 b1 = *reinterpret_cast<const float4*>(&Bs[kk][tx * 8 + 4]);
            a[0]=a0.x; a[1]=a0.y; a[2]=a0.z; a[3]=a0.w;
            a[4]=a1.x; a[5]=a1.y; a[6]=a1.z; a[7]=a1.w;
            b[0]=b0.x; b[1]=b0.y; b[2]=b0.z; b[3]=b0.w;
            b[4]=b1.x; b[5]=b1.y; b[6]=b1.z; b[7]=b1.w;
#pragma unroll
            for (int i = 0; i < 8; ++i)
#pragma unroll
                for (int j = 0; j < 8; ++j)
                    acc[i][j] = fmaf(a[i], b[j], acc[i][j]);
        }
        __syncthreads();
    }

    // ---- epilogue: bias (+ReLU), float4 stores ----
    float bv[8];
#pragma unroll
    for (int j = 0; j < 8; ++j) bv[j] = bias[tx * 8 + j];

#pragma unroll
    for (int i = 0; i < 8; ++i) {
        int grow = row0 + ty * 8 + i;
        if (grow < M) {
            float v[8];
#pragma unroll
            for (int j = 0; j < 8; ++j) {
                float z = acc[i][j] + bv[j];
                v[j] = do_relu ? fmaxf(z, 0.f) : z;
            }
            float* op = out + (size_t)grow * BN + tx * 8;
            *reinterpret_cast<float4*>(op)     = make_float4(v[0], v[1], v[2], v[3]);
            *reinterpret_cast<float4*>(op + 4) = make_float4(v[4], v[5], v[6], v[7]);
        }
    }
}

// ---------------------------------------------------------------------------
// Launch: 2 layers x (gather_mean, gemm). All plain launches; graph-capturable.
// Inputs (metadata order): feats f32[100000*128], neigh_idx i32[2*100000*16],
// Ws f32[2*256*128], bs f32[2*128]. Output f32[100000*128].
// ---------------------------------------------------------------------------
extern "C" void kernel_launch(void* const* d_in, const int* in_sizes, int n_in,
                              void* d_out, int out_size) {
    const float* feats = (const float*)d_in[0];
    const int*   nidx  = (const int*)d_in[1];
    const float* Ws    = (const float*)d_in[2];
    const float* bs    = (const float*)d_in[3];
    float* out = (float*)d_out;

    const int gather_blocks = (N_NODES * 32 + 255) / 256;   // 12500
    const int gemm_blocks   = (N_NODES + BM - 1) / BM;      // 782

    // Layer 0
    gather_mean_kernel<<<gather_blocks, 256>>>(feats, nidx, 0);
    sage_gemm_kernel<<<gemm_blocks, 256>>>(feats, Ws, bs, out, N_NODES, 0);

    // Layer 1
    gather_mean_kernel<<<gather_blocks, 256>>>(feats, nidx + (size_t)N_NODES * K_NEIGH, 1);
    sage_gemm_kernel<<<gemm_blocks, 256>>>(feats, Ws + 2 * D_FEAT * 128, bs + 128, out, N_NODES, 1);
}